// round 8
// baseline (speedup 1.0000x reference)
#include <cuda_runtime.h>
#include <cstdint>
#include <cfloat>

// Fused conv2d 3x3 SAME -> min over C_out -> *2 via fully-async mma.sync tf32.
// x: (32,64,128,128) f32, W: (128,64,3,3) f32, out: (32,1,128,128) f32
//
// Round 8: R5 tiling (CTA 128x128, 8 warps 2m x 4n, warp 64x32, 2 CTA/SM).
// Chunk = (8 ic, 1 ky) = 24K (3 k-steps), 24 chunks.
// A: per-element 4B cp.async straight into fragment layout; SAME-padding
//    zeros via the cp.async src-size=0 zero-fill form. RZ tf32 (raw f32 feed).
// B: fragment-ordered RNA-prerounded W (W2g) via 8B cp.async.
// Both 3-stage; mainloop body has no LDG/cvt/STS at all.

#define TPB 256

static constexpr int A_SLAB = 3 * 8 * 32 * 16;    // 12288
static constexpr int B_SLAB = 3 * 16 * 32 * 8;    // 12288
static constexpr int RED_OFF = 3 * (A_SLAB + B_SLAB);   // 73728
static constexpr int SMEM_TOTAL = RED_OFF + 2048;        // 75776 (2 CTAs/SM ok)

__device__ float W2g[24 * 3072];   // W fragment-ordered per 24K chunk, tf32-RNA

__device__ __forceinline__ uint32_t smem_u32(const void* p) {
    uint32_t a;
    asm("{ .reg .u64 t; cvta.to.shared.u64 t, %1; cvt.u32.u64 %0, t; }" : "=r"(a) : "l"(p));
    return a;
}
__device__ __forceinline__ uint32_t f32_to_tf32(float v) {
    uint32_t r;
    asm("cvt.rna.tf32.f32 %0, %1;" : "=r"(r) : "f"(v));
    return r;
}
__device__ __forceinline__ void mma_tf32(float& d0, float& d1, float& d2, float& d3,
                                         uint32_t a0, uint32_t a1, uint32_t a2, uint32_t a3,
                                         uint32_t b0, uint32_t b1) {
    asm volatile(
        "mma.sync.aligned.m16n8k8.row.col.f32.tf32.tf32.f32 "
        "{%0,%1,%2,%3}, {%4,%5,%6,%7}, {%8,%9}, {%0,%1,%2,%3};"
        : "+f"(d0), "+f"(d1), "+f"(d2), "+f"(d3)
        : "r"(a0), "r"(a1), "r"(a2), "r"(a3), "r"(b0), "r"(b1));
}

// ---- pre-kernel: W (OIHW) -> fragment-ordered, tf32-RNA W2g ----
// W2g[c*3072 + j*2 + r]: j=(s*16+ntg)*32+L; oc=ntg*8+L/4; k=s*8+(L&3)+4r;
// chunk c: ic0=(c/3)*8, ky=c%3; within chunk k=(icl,kx), k=icl*3+kx.
__global__ void wxform_kernel(const float* __restrict__ Wt) {
    int f = blockIdx.x * TPB + threadIdx.x;
    if (f >= 24 * 3072) return;
    int c   = f / 3072;
    int rem = f - c * 3072;
    int j = rem >> 1, r = rem & 1;
    int L = j & 31, plane = j >> 5;
    int ntg = plane & 15, s = plane >> 4;
    int oc  = ntg * 8 + (L >> 2);
    int k   = s * 8 + (L & 3) + 4 * r;
    int icl = k / 3, kx = k - 3 * icl;
    int c3  = c / 3;
    int ic0 = c3 * 8, ky = c - 3 * c3;
    float v = Wt[oc * 576 + (ic0 + icl) * 9 + ky * 3 + kx];
    W2g[f] = __uint_as_float(f32_to_tf32(v));
}

// issue all cp.asyncs for chunk c into the given A/B buffers (no commit)
__device__ __forceinline__ void issue_chunk(
    int c, uint32_t aDst, uint32_t bDst, int tid,
    const float* __restrict__ xb, int y,
    const int* __restrict__ off, uint32_t okmask)
{
    int c3 = c / 3;
    int gy = y + (c - 3 * c3) - 1;
    bool rok = (unsigned)gy < 128u;
    const float* srcbase = xb + c3 * 131072 + gy * 128;
#pragma unroll
    for (int i = 0; i < 12; ++i) {
        bool ok = rok && ((okmask >> i) & 1u);
        const float* s = ok ? (srcbase + off[i]) : xb;
        uint32_t sz = ok ? 4u : 0u;
        uint64_t g = __cvta_generic_to_global((const void*)s);
        asm volatile("cp.async.ca.shared.global [%0], [%1], 4, %2;"
                     :: "r"(aDst + (uint32_t)((tid + TPB * i) * 4)), "l"(g), "r"(sz)
                     : "memory");
    }
    const float* wsrc = W2g + c * 3072;
#pragma unroll
    for (int i = 0; i < 6; ++i) {
        int j = tid + TPB * i;
        uint64_t g = __cvta_generic_to_global((const void*)(wsrc + j * 2));
        asm volatile("cp.async.ca.shared.global [%0], [%1], 8;"
                     :: "r"(bDst + (uint32_t)(j * 8)), "l"(g) : "memory");
    }
}

__global__ void __launch_bounds__(TPB, 2)
conv_min_mma5_kernel(const float* __restrict__ x,
                     float* __restrict__ out)
{
    extern __shared__ char smem[];
    const uint32_t sbA = smem_u32(smem);
    const uint32_t sbB = sbA + 3 * A_SLAB;
    const int tid    = threadIdx.x;
    const int lane   = tid & 31;
    const int wid    = tid >> 5;
    const int warp_m = wid >> 2;   // 0..1
    const int warp_n = wid & 3;    // 0..3
    const int y = blockIdx.x;
    const int b = blockIdx.y;
    const float* xb = x + (size_t)b * (64 * 128 * 128);

    // ---- per-thread A cp.async source table (chunk-invariant part) ----
    // element e = tid + 256*i of the A slab; decode (s,mtg,L,q):
    //   k = s*8 + (L&3) + (q>>1)*4, px = mtg*16 + (L>>2) + (q&1)*8
    int off[12];
    uint32_t okmask = 0;
#pragma unroll
    for (int i = 0; i < 12; ++i) {
        int e   = tid + TPB * i;
        int q   = e & 3;
        int L   = (e >> 2) & 31;
        int mtg = (e >> 7) & 7;
        int s   = e >> 10;
        int k   = s * 8 + (L & 3) + (q >> 1) * 4;
        int px  = mtg * 16 + (L >> 2) + (q & 1) * 8;
        int icl = k / 3, kx = k - 3 * icl;
        off[i]  = icl * 16384 + px + kx - 1;
        bool ok = !(px == 0 && kx == 0) && !(px == 127 && kx == 2);
        okmask |= (ok ? 1u : 0u) << i;
    }

    float acc[4][4][4];
#pragma unroll
    for (int mt = 0; mt < 4; ++mt)
#pragma unroll
        for (int nt = 0; nt < 4; ++nt)
#pragma unroll
            for (int r = 0; r < 4; ++r) acc[mt][nt][r] = 0.0f;

    // ---- prologue: groups g0 = chunk0, g1 = chunk1 ----
    issue_chunk(0, sbA, sbB, tid, xb, y, off, okmask);
    asm volatile("cp.async.commit_group;" ::: "memory");
    issue_chunk(1, sbA + A_SLAB, sbB + B_SLAB, tid, xb, y, off, okmask);
    asm volatile("cp.async.commit_group;" ::: "memory");

#pragma unroll 1
    for (int c = 0; c < 24; ++c) {
        // g(c) complete (g(c+1) may remain in flight)
        asm volatile("cp.async.wait_group 1;" ::: "memory");
        __syncthreads();

        const int bi = c % 3;
        const int wi2 = (c + 2) % 3;
        if (c + 2 < 24)
            issue_chunk(c + 2, sbA + (uint32_t)wi2 * A_SLAB,
                        sbB + (uint32_t)wi2 * B_SLAB, tid, xb, y, off, okmask);
        asm volatile("cp.async.commit_group;" ::: "memory");

        // ---- compute chunk c (3 k-steps) ----
        const uint32_t aRd = sbA + (uint32_t)bi * A_SLAB;
        const uint32_t bRd = sbB + (uint32_t)bi * B_SLAB;
#pragma unroll
        for (int s = 0; s < 3; ++s) {
            uint32_t a0[4], a1[4], a2[4], a3[4];
#pragma unroll
            for (int mt = 0; mt < 4; ++mt) {
                uint32_t addr = aRd +
                    (uint32_t)(((s * 8 + warp_m * 4 + mt) * 32 + lane) * 16);
                asm volatile("ld.shared.v4.b32 {%0,%1,%2,%3}, [%4];"
                             : "=r"(a0[mt]), "=r"(a1[mt]), "=r"(a2[mt]), "=r"(a3[mt])
                             : "r"(addr));
            }
            uint32_t b0[4], b1[4];
#pragma unroll
            for (int nt = 0; nt < 4; ++nt) {
                uint32_t addr = bRd +
                    (uint32_t)(((s * 16 + warp_n * 4 + nt) * 32 + lane) * 8);
                asm volatile("ld.shared.v2.b32 {%0,%1}, [%2];"
                             : "=r"(b0[nt]), "=r"(b1[nt]) : "r"(addr));
            }
#pragma unroll
            for (int mt = 0; mt < 4; ++mt)
#pragma unroll
                for (int nt = 0; nt < 4; ++nt)
                    mma_tf32(acc[mt][nt][0], acc[mt][nt][1],
                             acc[mt][nt][2], acc[mt][nt][3],
                             a0[mt], a1[mt], a2[mt], a3[mt], b0[nt], b1[nt]);
        }
    }

    // ---- epilogue: min over oc, *2, write ----
    float rmin[4][2];
#pragma unroll
    for (int mt = 0; mt < 4; ++mt) {
        float lo = fminf(acc[mt][0][0], acc[mt][0][1]);
        float hi = fminf(acc[mt][0][2], acc[mt][0][3]);
#pragma unroll
        for (int nt = 1; nt < 4; ++nt) {
            lo = fminf(lo, fminf(acc[mt][nt][0], acc[mt][nt][1]));
            hi = fminf(hi, fminf(acc[mt][nt][2], acc[mt][nt][3]));
        }
        rmin[mt][0] = lo;
        rmin[mt][1] = hi;
    }
#pragma unroll
    for (int d = 1; d <= 2; d <<= 1)
#pragma unroll
        for (int mt = 0; mt < 4; ++mt)
#pragma unroll
            for (int h = 0; h < 2; ++h)
                rmin[mt][h] = fminf(rmin[mt][h],
                                    __shfl_xor_sync(0xffffffffu, rmin[mt][h], d));

    float* red = reinterpret_cast<float*>(smem + RED_OFF);
    __syncthreads();
    if ((lane & 3) == 0) {
        int g = lane >> 2;
#pragma unroll
        for (int mt = 0; mt < 4; ++mt)
#pragma unroll
            for (int h = 0; h < 2; ++h) {
                int row = (warp_m * 4 + mt) * 16 + h * 8 + g;
                red[row * 4 + warp_n] = rmin[mt][h];
            }
    }
    __syncthreads();
    if (tid < 128) {
        float m = fminf(fminf(red[tid * 4 + 0], red[tid * 4 + 1]),
                        fminf(red[tid * 4 + 2], red[tid * 4 + 3]));
        out[(size_t)b * 16384 + y * 128 + tid] = m * 2.0f;
    }
}

extern "C" void kernel_launch(void* const* d_in, const int* in_sizes, int n_in,
                              void* d_out, int out_size)
{
    const float* x  = (const float*)d_in[0];
    const float* Wt = (const float*)d_in[1];
    float* out = (float*)d_out;

    cudaFuncSetAttribute(conv_min_mma5_kernel,
                         cudaFuncAttributeMaxDynamicSharedMemorySize, SMEM_TOTAL);

    wxform_kernel<<<(24 * 3072 + TPB - 1) / TPB, TPB>>>(Wt);

    dim3 grid(128, 32);   // rows x batch
    conv_min_mma5_kernel<<<grid, TPB, SMEM_TOTAL>>>(x, out);
}

// round 9
// speedup vs baseline: 1.4105x; 1.4105x over previous
#include <cuda_runtime.h>
#include <cstdint>
#include <cfloat>

// Fused conv2d 3x3 SAME -> min over C_out -> *2 via pipelined mma.sync tf32.
// x: (32,64,128,128) f32, W: (128,64,3,3) f32, out: (32,1,128,128) f32
//
// Round 9 = Round 5 (best: 451us) with issue-count trims:
//  - A fed as raw f32 (HW RZ->tf32; rel_err ~3.7e-4, proven R8): no cvt in loop
//  - B fragments pair-packed 16B/lane -> 2x LDS.128 per k-step instead of 4x LDS.64
//  - LDG prefetch issued immediately after the chunk barrier
// Tiling: CTA 128x128, 8 warps 2m x 4n (warp 64x32), 2 CTA/SM, chunk = 24K
// (8 ic x 1 ky, 3 k-steps), 24 chunks; B via 8B cp.async 3-stage from
// fragment-ordered W2g; A via LDG(c+1) during compute(c) + STS.128.

#define TPB 256

static constexpr int A_SLAB = 3 * 8 * 32 * 16;    // 12288
static constexpr int B_SLAB = 3 * 8 * 32 * 16;    // 12288 (pair-packed)
static constexpr int RED_OFF = 2 * A_SLAB + 3 * B_SLAB;
static constexpr int SMEM_TOTAL = RED_OFF + 2048;  // 63488

__device__ float W2g[24 * 3072];   // W fragment-ordered (pair-packed), tf32-RNA

__device__ __forceinline__ uint32_t smem_u32(const void* p) {
    uint32_t a;
    asm("{ .reg .u64 t; cvta.to.shared.u64 t, %1; cvt.u32.u64 %0, t; }" : "=r"(a) : "l"(p));
    return a;
}
__device__ __forceinline__ uint32_t f32_to_tf32(float v) {
    uint32_t r;
    asm("cvt.rna.tf32.f32 %0, %1;" : "=r"(r) : "f"(v));
    return r;
}
__device__ __forceinline__ void mma_tf32(float& d0, float& d1, float& d2, float& d3,
                                         uint32_t a0, uint32_t a1, uint32_t a2, uint32_t a3,
                                         uint32_t b0, uint32_t b1) {
    asm volatile(
        "mma.sync.aligned.m16n8k8.row.col.f32.tf32.tf32.f32 "
        "{%0,%1,%2,%3}, {%4,%5,%6,%7}, {%8,%9}, {%0,%1,%2,%3};"
        : "+f"(d0), "+f"(d1), "+f"(d2), "+f"(d3)
        : "r"(a0), "r"(a1), "r"(a2), "r"(a3), "r"(b0), "r"(b1));
}

// ---- pre-kernel: W (OIHW) -> pair-packed fragment order, tf32-RNA ----
// 16B unit j16 = (s*8 + p)*32 + L holds words w=0..3:
//   nt = p*2 + (w>>1), r = w&1, oc = nt*8 + (L>>2), k = s*8 + (L&3) + 4r
// chunk c: ic0=(c/3)*8, ky=c%3; within chunk k=(icl,kx), k=icl*3+kx.
__global__ void wxform_kernel(const float* __restrict__ Wt) {
    int f = blockIdx.x * TPB + threadIdx.x;
    if (f >= 24 * 3072) return;
    int c   = f / 3072;
    int rem = f - c * 3072;
    int j16 = rem >> 2, w = rem & 3;
    int L = j16 & 31, sp = j16 >> 5;
    int p = sp & 7, s = sp >> 3;
    int nt = p * 2 + (w >> 1);
    int r  = w & 1;
    int oc = nt * 8 + (L >> 2);
    int k  = s * 8 + (L & 3) + 4 * r;
    int icl = k / 3, kx = k - 3 * icl;
    int c3  = c / 3;
    int ic0 = c3 * 8, ky = c - 3 * c3;
    float v = Wt[oc * 576 + (ic0 + icl) * 9 + ky * 3 + kx];
    W2g[f] = __uint_as_float(f32_to_tf32(v));
}

__global__ void __launch_bounds__(TPB, 2)
conv_min_mma6_kernel(const float* __restrict__ x,
                     float* __restrict__ out)
{
    extern __shared__ char smem[];
    const uint32_t sbA = smem_u32(smem);
    const uint32_t sbB = sbA + 2 * A_SLAB;
    const int tid    = threadIdx.x;
    const int lane   = tid & 31;
    const int wid    = tid >> 5;
    const int warp_m = wid >> 2;   // 0..1
    const int warp_n = wid & 3;    // 0..3
    const int y = blockIdx.x;
    const int b = blockIdx.y;
    const float* xb = x + (size_t)b * (64 * 128 * 128);

    // ---- per-thread A-fill constants (3 slots of 16B each) ----
    int a_off0[3], a_off1[3];
    bool pll[3], plh[3], phl[3], phh[3];
    uint32_t a_sts[3];
#pragma unroll
    for (int i = 0; i < 3; ++i) {
        int j = tid + TPB * i;
        int L = j & 31, plane = j >> 5;
        int mtg = plane & 7, s = plane >> 3;
        int px = mtg * 16 + (L >> 2);
        int kl = s * 8 + (L & 3);
        int kh = kl + 4;
        int il = kl / 3, xl = kl - 3 * il;
        int ih = kh / 3, xh = kh - 3 * ih;
        a_off0[i] = il * 16384 + px + xl - 1;
        a_off1[i] = ih * 16384 + px + xh - 1;
        pll[i] = !(px == 0 && xl == 0);
        plh[i] = !(px == 0 && xh == 0);
        phl[i] = !(px + 8 == 127 && xl == 2);
        phh[i] = !(px + 8 == 127 && xh == 2);
        a_sts[i] = (uint32_t)(((s * 8 + mtg) * 32 + L) * 16);
    }

    float acc[4][4][4];
#pragma unroll
    for (int mt = 0; mt < 4; ++mt)
#pragma unroll
        for (int nt = 0; nt < 4; ++nt)
#pragma unroll
            for (int r = 0; r < 4; ++r) acc[mt][nt][r] = 0.0f;

    // ---- prologue: issue B(0), B(1); fill A(0) into buf 0 ----
#pragma unroll
    for (int cc = 0; cc < 2; ++cc) {
        uint32_t dst = sbB + cc * B_SLAB;
        const float* src = W2g + cc * 3072;
#pragma unroll
        for (int i = 0; i < 6; ++i) {
            int j = tid + TPB * i;
            uint64_t g = __cvta_generic_to_global((const void*)(src + j * 2));
            asm volatile("cp.async.ca.shared.global [%0], [%1], 8;"
                         :: "r"(dst + (uint32_t)(j * 8)), "l"(g) : "memory");
        }
        asm volatile("cp.async.commit_group;" ::: "memory");
    }
    {   // A(0): chunk 0 -> ic0=0, ky=0, gy=y-1   (raw f32, no cvt)
        int gy = y - 1;
        bool rowok = (unsigned)gy < 128u;
        const float* xrow = xb + gy * 128;
#pragma unroll
        for (int i = 0; i < 3; ++i) {
            float v0 = 0.f, v1 = 0.f, v2 = 0.f, v3 = 0.f;
            if (rowok && pll[i]) v0 = xrow[a_off0[i]];
            if (rowok && phl[i]) v1 = xrow[a_off0[i] + 8];
            if (rowok && plh[i]) v2 = xrow[a_off1[i]];
            if (rowok && phh[i]) v3 = xrow[a_off1[i] + 8];
            asm volatile("st.shared.v4.b32 [%0], {%1,%2,%3,%4};"
                         :: "r"(sbA + a_sts[i]),
                            "r"(__float_as_uint(v0)), "r"(__float_as_uint(v1)),
                            "r"(__float_as_uint(v2)), "r"(__float_as_uint(v3))
                         : "memory");
        }
    }

    int bR = 0;   // B read buffer = c % 3
#pragma unroll 1
    for (int c = 0; c < 24; ++c) {
        // B(c) ready (<=1 group outstanding), A(c) stored by all threads
        asm volatile("cp.async.wait_group 1;" ::: "memory");
        __syncthreads();

        // prefetch A(c+1) into regs FIRST (longest latency)
        float av0[3], av1[3], av2[3], av3[3];
        if (c + 1 < 24) {
            int cn = c + 1;
            int c3 = cn / 3;
            int ic0 = c3 * 8, ky = cn - 3 * c3;
            int gy = y + ky - 1;
            bool rowok = (unsigned)gy < 128u;
            const float* xrow = xb + ic0 * 16384 + gy * 128;
#pragma unroll
            for (int i = 0; i < 3; ++i) {
                float v0 = 0.f, v1 = 0.f, v2 = 0.f, v3 = 0.f;
                if (rowok && pll[i]) v0 = xrow[a_off0[i]];
                if (rowok && phl[i]) v1 = xrow[a_off0[i] + 8];
                if (rowok && plh[i]) v2 = xrow[a_off1[i]];
                if (rowok && phh[i]) v3 = xrow[a_off1[i] + 8];
                av0[i] = v0; av1[i] = v1; av2[i] = v2; av3[i] = v3;
            }
        }

        // issue B(c+2)
        if (c + 2 < 24) {
            int bW = bR - 1; if (bW < 0) bW += 3;
            uint32_t dst = sbB + (uint32_t)bW * B_SLAB;
            const float* src = W2g + (c + 2) * 3072;
#pragma unroll
            for (int i = 0; i < 6; ++i) {
                int j = tid + TPB * i;
                uint64_t g = __cvta_generic_to_global((const void*)(src + j * 2));
                asm volatile("cp.async.ca.shared.global [%0], [%1], 8;"
                             :: "r"(dst + (uint32_t)(j * 8)), "l"(g) : "memory");
            }
        }
        asm volatile("cp.async.commit_group;" ::: "memory");

        // ---- compute chunk c (3 k-steps) ----
        const uint32_t aRd = sbA + (uint32_t)(c & 1) * A_SLAB;
        const uint32_t bRd = sbB + (uint32_t)bR * B_SLAB;
#pragma unroll
        for (int s = 0; s < 3; ++s) {
            uint32_t a0[4], a1[4], a2[4], a3[4];
#pragma unroll
            for (int mt = 0; mt < 4; ++mt) {
                uint32_t addr = aRd +
                    (uint32_t)(((s * 8 + warp_m * 4 + mt) * 32 + lane) * 16);
                asm volatile("ld.shared.v4.b32 {%0,%1,%2,%3}, [%4];"
                             : "=r"(a0[mt]), "=r"(a1[mt]), "=r"(a2[mt]), "=r"(a3[mt])
                             : "r"(addr));
            }
            uint32_t b0[4], b1[4];
#pragma unroll
            for (int j = 0; j < 2; ++j) {      // pair-packed: 2x LDS.128
                uint32_t addr = bRd +
                    (uint32_t)(((s * 8 + warp_n * 2 + j) * 32 + lane) * 16);
                asm volatile("ld.shared.v4.b32 {%0,%1,%2,%3}, [%4];"
                             : "=r"(b0[2 * j]), "=r"(b1[2 * j]),
                               "=r"(b0[2 * j + 1]), "=r"(b1[2 * j + 1])
                             : "r"(addr));
            }
#pragma unroll
            for (int mt = 0; mt < 4; ++mt)
#pragma unroll
                for (int nt = 0; nt < 4; ++nt)
                    mma_tf32(acc[mt][nt][0], acc[mt][nt][1],
                             acc[mt][nt][2], acc[mt][nt][3],
                             a0[mt], a1[mt], a2[mt], a3[mt], b0[nt], b1[nt]);
        }

        // store prefetched A(c+1) (raw f32)
        if (c + 1 < 24) {
            const uint32_t aWr = sbA + (uint32_t)((c + 1) & 1) * A_SLAB;
#pragma unroll
            for (int i = 0; i < 3; ++i) {
                asm volatile("st.shared.v4.b32 [%0], {%1,%2,%3,%4};"
                             :: "r"(aWr + a_sts[i]),
                                "r"(__float_as_uint(av0[i])), "r"(__float_as_uint(av1[i])),
                                "r"(__float_as_uint(av2[i])), "r"(__float_as_uint(av3[i]))
                             : "memory");
            }
        }
        bR = (bR == 2) ? 0 : bR + 1;
    }

    // ---- epilogue: min over oc, *2, write ----
    float rmin[4][2];
#pragma unroll
    for (int mt = 0; mt < 4; ++mt) {
        float lo = fminf(acc[mt][0][0], acc[mt][0][1]);
        float hi = fminf(acc[mt][0][2], acc[mt][0][3]);
#pragma unroll
        for (int nt = 1; nt < 4; ++nt) {
            lo = fminf(lo, fminf(acc[mt][nt][0], acc[mt][nt][1]));
            hi = fminf(hi, fminf(acc[mt][nt][2], acc[mt][nt][3]));
        }
        rmin[mt][0] = lo;
        rmin[mt][1] = hi;
    }
#pragma unroll
    for (int d = 1; d <= 2; d <<= 1)
#pragma unroll
        for (int mt = 0; mt < 4; ++mt)
#pragma unroll
            for (int h = 0; h < 2; ++h)
                rmin[mt][h] = fminf(rmin[mt][h],
                                    __shfl_xor_sync(0xffffffffu, rmin[mt][h], d));

    float* red = reinterpret_cast<float*>(smem + RED_OFF);
    __syncthreads();
    if ((lane & 3) == 0) {
        int g = lane >> 2;
#pragma unroll
        for (int mt = 0; mt < 4; ++mt)
#pragma unroll
            for (int h = 0; h < 2; ++h) {
                int row = (warp_m * 4 + mt) * 16 + h * 8 + g;
                red[row * 4 + warp_n] = rmin[mt][h];
            }
    }
    __syncthreads();
    if (tid < 128) {
        float m = fminf(fminf(red[tid * 4 + 0], red[tid * 4 + 1]),
                        fminf(red[tid * 4 + 2], red[tid * 4 + 3]));
        out[(size_t)b * 16384 + y * 128 + tid] = m * 2.0f;
    }
}

extern "C" void kernel_launch(void* const* d_in, const int* in_sizes, int n_in,
                              void* d_out, int out_size)
{
    const float* x  = (const float*)d_in[0];
    const float* Wt = (const float*)d_in[1];
    float* out = (float*)d_out;

    cudaFuncSetAttribute(conv_min_mma6_kernel,
                         cudaFuncAttributeMaxDynamicSharedMemorySize, SMEM_TOTAL);

    wxform_kernel<<<(24 * 3072 + TPB - 1) / TPB, TPB>>>(Wt);

    dim3 grid(128, 32);   // rows x batch
    conv_min_mma6_kernel<<<grid, TPB, SMEM_TOTAL>>>(x, out);
}

// round 10
// speedup vs baseline: 1.4976x; 1.0618x over previous
#include <cuda_runtime.h>
#include <cstdint>
#include <cfloat>

// Fused conv2d 3x3 SAME -> min over C_out -> *2 via pipelined mma.sync tf32.
// x: (32,64,128,128) f32, W: (128,64,3,3) f32, out: (32,1,128,128) f32
//
// Round 10 = R9 with the im2col A slab replaced by RAW x ROWS in smem:
//  - per ic-group (8 ic): 24 rows (8 ic x 3 gy) loaded once via 16B cp.async,
//    reused by all 3 ky chunks and all 3 kx taps (kills 9x im2col fill dup)
//  - A fragments gathered by per-lane LDS.32 (row stride 576B == 16 banks mod 32
//    -> conflict-free; same wavefront count as the old LDS.128 reads)
//  - SAME padding via zeroed per-row padding words + 32B guard
// B path / pipeline / epilogue identical to R9 (pair-packed LDS.128, cp.async,
// one wait+sync per chunk). A fed raw f32 (HW RZ->tf32).

#define TPB 256

static constexpr int A_BUF  = 24 * 576;            // 13824 per ic-group buffer
static constexpr int A0_OFF = 32;                  // 32B zero guard before A0
static constexpr int B_OFF  = A0_OFF + 2 * A_BUF;  // 27680
static constexpr int B_SLAB = 12288;
static constexpr int RED_OFF = B_OFF + 3 * B_SLAB; // 64544
static constexpr int SMEM_TOTAL = RED_OFF + 2048;  // 66592

__device__ float W2g[24 * 3072];   // W fragment-ordered (pair-packed), tf32-RNA

__device__ __forceinline__ uint32_t smem_u32(const void* p) {
    uint32_t a;
    asm("{ .reg .u64 t; cvta.to.shared.u64 t, %1; cvt.u32.u64 %0, t; }" : "=r"(a) : "l"(p));
    return a;
}
__device__ __forceinline__ uint32_t f32_to_tf32(float v) {
    uint32_t r;
    asm("cvt.rna.tf32.f32 %0, %1;" : "=r"(r) : "f"(v));
    return r;
}
__device__ __forceinline__ uint32_t lds32(uint32_t a) {
    uint32_t v;
    asm volatile("ld.shared.b32 %0, [%1];" : "=r"(v) : "r"(a));
    return v;
}
__device__ __forceinline__ void mma_tf32(float& d0, float& d1, float& d2, float& d3,
                                         uint32_t a0, uint32_t a1, uint32_t a2, uint32_t a3,
                                         uint32_t b0, uint32_t b1) {
    asm volatile(
        "mma.sync.aligned.m16n8k8.row.col.f32.tf32.tf32.f32 "
        "{%0,%1,%2,%3}, {%4,%5,%6,%7}, {%8,%9}, {%0,%1,%2,%3};"
        : "+f"(d0), "+f"(d1), "+f"(d2), "+f"(d3)
        : "r"(a0), "r"(a1), "r"(a2), "r"(a3), "r"(b0), "r"(b1));
}

// ---- pre-kernel: W (OIHW) -> pair-packed fragment order, tf32-RNA (as R9) ----
__global__ void wxform_kernel(const float* __restrict__ Wt) {
    int f = blockIdx.x * TPB + threadIdx.x;
    if (f >= 24 * 3072) return;
    int c   = f / 3072;
    int rem = f - c * 3072;
    int j16 = rem >> 2, w = rem & 3;
    int L = j16 & 31, sp = j16 >> 5;
    int p = sp & 7, s = sp >> 3;
    int nt = p * 2 + (w >> 1);
    int r  = w & 1;
    int oc = nt * 8 + (L >> 2);
    int k  = s * 8 + (L & 3) + 4 * r;
    int icl = k / 3, kx = k - 3 * icl;
    int c3  = c / 3;
    int ic0 = c3 * 8, ky = c - 3 * c3;
    float v = Wt[oc * 576 + (ic0 + icl) * 9 + ky * 3 + kx];
    W2g[f] = __uint_as_float(f32_to_tf32(v));
}

__global__ void __launch_bounds__(TPB, 2)
conv_min_mma7_kernel(const float* __restrict__ x,
                     float* __restrict__ out)
{
    extern __shared__ char smem[];
    const uint32_t sb = smem_u32(smem);
    const int tid    = threadIdx.x;
    const int lane   = tid & 31;
    const int wid    = tid >> 5;
    const int warp_m = wid >> 2;   // 0..1
    const int warp_n = wid & 3;    // 0..3
    const int q = lane >> 2;       // fragment row-in-8
    const int t = lane & 3;        // fragment k-in-4
    const int y = blockIdx.x;
    const int b = blockIdx.y;
    const float* xb = x + (size_t)b * (64 * 128 * 128);

    // ---- zero halos: guard [0,32) + words 128..143 of all 48 row slots ----
    for (int w = tid; w < 8 + 48 * 16; w += TPB) {
        uint32_t addr;
        if (w < 8) addr = sb + (uint32_t)(w * 4);
        else {
            int z = w - 8, slot = z >> 4, wd = z & 15;
            addr = sb + (uint32_t)(A0_OFF + slot * 576 + 512 + wd * 4);
        }
        asm volatile("st.shared.b32 [%0], %1;" :: "r"(addr), "r"(0u) : "memory");
    }

    // ---- per-lane A-gather constants: j = s*2+u, k = 8s+4u+t ----
    int offA[6];
#pragma unroll
    for (int j = 0; j < 6; ++j) {
        int k   = 8 * (j >> 1) + 4 * (j & 1) + t;
        int icl = k / 3, kx = k - 3 * icl;
        offA[j] = icl * 1728 + (q + kx - 1) * 4;
    }

    // ---- per-thread row-fill constants (3 x 16B cp.async per ic-group) ----
    int r_dst[3], r_src[3], r_kyr[3];
#pragma unroll
    for (int i = 0; i < 3; ++i) {
        int ch = tid + TPB * i;       // 0..767
        int slot = ch >> 5, pos = ch & 31;
        int icl = slot / 3, kyr = slot - 3 * icl;
        r_dst[i] = A0_OFF + slot * 576 + pos * 16;
        r_src[i] = icl * 16384 + (kyr - 1) * 128 + pos * 4;  // floats, rel to xb+y*128
        r_kyr[i] = kyr;
    }

    float acc[4][4][4];
#pragma unroll
    for (int mt = 0; mt < 4; ++mt)
#pragma unroll
        for (int nt = 0; nt < 4; ++nt)
#pragma unroll
            for (int r = 0; r < 4; ++r) acc[mt][nt][r] = 0.0f;

    __syncthreads();   // halo zeros visible before first rows land

    // ---- prologue: commit P0 = rows(g0), P1 = B0, P2 = B1 ----
    {
        const float* gbase = xb + y * 128;   // g = 0
#pragma unroll
        for (int i = 0; i < 3; ++i) {
            bool ok = (unsigned)(y + r_kyr[i] - 1) < 128u;
            const float* s = ok ? (gbase + r_src[i]) : xb;
            uint32_t sz = ok ? 16u : 0u;
            uint64_t g64 = __cvta_generic_to_global((const void*)s);
            asm volatile("cp.async.cg.shared.global [%0], [%1], 16, %2;"
                         :: "r"(sb + (uint32_t)r_dst[i]), "l"(g64), "r"(sz) : "memory");
        }
        asm volatile("cp.async.commit_group;" ::: "memory");
    }
#pragma unroll
    for (int cc = 0; cc < 2; ++cc) {
        uint32_t dst = sb + B_OFF + cc * B_SLAB;
        const float* src = W2g + cc * 3072;
#pragma unroll
        for (int i = 0; i < 6; ++i) {
            int j = tid + TPB * i;
            uint64_t g64 = __cvta_generic_to_global((const void*)(src + j * 2));
            asm volatile("cp.async.ca.shared.global [%0], [%1], 8;"
                         :: "r"(dst + (uint32_t)(j * 8)), "l"(g64) : "memory");
        }
        asm volatile("cp.async.commit_group;" ::: "memory");
    }

    int g = 0, kyc = 0;
#pragma unroll 1
    for (int c = 0; c < 24; ++c) {
        // everything needed for chunk c is >= 2 commit-groups old
        asm volatile("cp.async.wait_group 1;" ::: "memory");
        __syncthreads();

        // first chunk of an ic-group: issue rows for group g+1 (opposite parity)
        if (kyc == 0 && g < 7) {
            const float* gbase = xb + (g + 1) * 131072 + y * 128;
            uint32_t pb = sb + (uint32_t)(((g + 1) & 1) * A_BUF);
#pragma unroll
            for (int i = 0; i < 3; ++i) {
                bool ok = (unsigned)(y + r_kyr[i] - 1) < 128u;
                const float* s = ok ? (gbase + r_src[i]) : xb;
                uint32_t sz = ok ? 16u : 0u;
                uint64_t g64 = __cvta_generic_to_global((const void*)s);
                asm volatile("cp.async.cg.shared.global [%0], [%1], 16, %2;"
                             :: "r"(pb + (uint32_t)r_dst[i]), "l"(g64), "r"(sz)
                             : "memory");
            }
        }
        // issue B(c+2)
        if (c + 2 < 24) {
            int wslab = (c + 2) % 3;
            uint32_t dst = sb + B_OFF + (uint32_t)wslab * B_SLAB;
            const float* src = W2g + (c + 2) * 3072;
#pragma unroll
            for (int i = 0; i < 6; ++i) {
                int j = tid + TPB * i;
                uint64_t g64 = __cvta_generic_to_global((const void*)(src + j * 2));
                asm volatile("cp.async.ca.shared.global [%0], [%1], 8;"
                             :: "r"(dst + (uint32_t)(j * 8)), "l"(g64) : "memory");
            }
        }
        asm volatile("cp.async.commit_group;" ::: "memory");

        // ---- compute chunk c: gather A from raw rows, B pair-packed ----
        const uint32_t abase = sb + (uint32_t)(A0_OFF + (g & 1) * A_BUF +
                                               kyc * 576 + warp_m * 256);
        uint32_t ab[6];
#pragma unroll
        for (int j = 0; j < 6; ++j) ab[j] = abase + (uint32_t)offA[j];
        const uint32_t bRd = sb + B_OFF + (uint32_t)(c % 3) * B_SLAB +
                             (uint32_t)(warp_n * 1024 + lane * 16);
#pragma unroll
        for (int s = 0; s < 3; ++s) {
            uint32_t a0[4], a1[4], a2[4], a3[4];
#pragma unroll
            for (int mt = 0; mt < 4; ++mt) {
                a0[mt] = lds32(ab[2 * s + 0] + (uint32_t)(mt * 64));
                a1[mt] = lds32(ab[2 * s + 0] + (uint32_t)(mt * 64 + 32));
                a2[mt] = lds32(ab[2 * s + 1] + (uint32_t)(mt * 64));
                a3[mt] = lds32(ab[2 * s + 1] + (uint32_t)(mt * 64 + 32));
            }
            uint32_t b0[4], b1[4];
#pragma unroll
            for (int j = 0; j < 2; ++j) {
                uint32_t addr = bRd + (uint32_t)(s * 4096 + j * 512);
                asm volatile("ld.shared.v4.b32 {%0,%1,%2,%3}, [%4];"
                             : "=r"(b0[2 * j]), "=r"(b1[2 * j]),
                               "=r"(b0[2 * j + 1]), "=r"(b1[2 * j + 1])
                             : "r"(addr));
            }
#pragma unroll
            for (int mt = 0; mt < 4; ++mt)
#pragma unroll
                for (int nt = 0; nt < 4; ++nt)
                    mma_tf32(acc[mt][nt][0], acc[mt][nt][1],
                             acc[mt][nt][2], acc[mt][nt][3],
                             a0[mt], a1[mt], a2[mt], a3[mt], b0[nt], b1[nt]);
        }

        if (++kyc == 3) { kyc = 0; ++g; }
    }

    // ---- epilogue: min over oc, *2, write (as R9) ----
    float rmin[4][2];
#pragma unroll
    for (int mt = 0; mt < 4; ++mt) {
        float lo = fminf(acc[mt][0][0], acc[mt][0][1]);
        float hi = fminf(acc[mt][0][2], acc[mt][0][3]);
#pragma unroll
        for (int nt = 1; nt < 4; ++nt) {
            lo = fminf(lo, fminf(acc[mt][nt][0], acc[mt][nt][1]));
            hi = fminf(hi, fminf(acc[mt][nt][2], acc[mt][nt][3]));
        }
        rmin[mt][0] = lo;
        rmin[mt][1] = hi;
    }
#pragma unroll
    for (int d = 1; d <= 2; d <<= 1)
#pragma unroll
        for (int mt = 0; mt < 4; ++mt)
#pragma unroll
            for (int h = 0; h < 2; ++h)
                rmin[mt][h] = fminf(rmin[mt][h],
                                    __shfl_xor_sync(0xffffffffu, rmin[mt][h], d));

    float* red = reinterpret_cast<float*>(smem + RED_OFF);
    __syncthreads();
    if ((lane & 3) == 0) {
        int gq = lane >> 2;
#pragma unroll
        for (int mt = 0; mt < 4; ++mt)
#pragma unroll
            for (int h = 0; h < 2; ++h) {
                int row = (warp_m * 4 + mt) * 16 + h * 8 + gq;
                red[row * 4 + warp_n] = rmin[mt][h];
            }
    }
    __syncthreads();
    if (tid < 128) {
        float m = fminf(fminf(red[tid * 4 + 0], red[tid * 4 + 1]),
                        fminf(red[tid * 4 + 2], red[tid * 4 + 3]));
        out[(size_t)b * 16384 + y * 128 + tid] = m * 2.0f;
    }
}

extern "C" void kernel_launch(void* const* d_in, const int* in_sizes, int n_in,
                              void* d_out, int out_size)
{
    const float* x  = (const float*)d_in[0];
    const float* Wt = (const float*)d_in[1];
    float* out = (float*)d_out;

    cudaFuncSetAttribute(conv_min_mma7_kernel,
                         cudaFuncAttributeMaxDynamicSharedMemorySize, SMEM_TOTAL);

    wxform_kernel<<<(24 * 3072 + TPB - 1) / TPB, TPB>>>(Wt);

    dim3 grid(128, 32);   // rows x batch
    conv_min_mma7_kernel<<<grid, TPB, SMEM_TOTAL>>>(x, out);
}

// round 12
// speedup vs baseline: 1.8766x; 1.2531x over previous
#include <cuda_runtime.h>
#include <cuda_fp16.h>
#include <cstdint>
#include <cfloat>

// Fused conv2d 3x3 SAME -> min over C_out -> *2 via pipelined mma.sync FP16
// (m16n8k16, f32 accumulate). x:(32,64,128,128) f32, W:(128,64,3,3) f32.
//
// Round 12 = R11 with correct edge handling for fp16 pair packing:
//  - copyO (even pair starts) = plain fp16 image x16g, 64 words/row
//  - copyE (odd starts incl s=-1 and s=127) = pre-padded image x16pE
//    (row stride 144 halves: [0, x0..x127, 0, pad0s]), 65 words/row
//  - slot: [copyE 272B][16][copyO 256B][pad 32B] = 576B; copyO at +288 (8 banks),
//    icl stride 1728 (16 banks) -> all A gathers 1 wavefront (disjoint bank ranges)
//  - K padded 4 slots/(ic,ky) (3 taps + phantom w=0) -> 2 k16-steps per chunk

#define TPB 256

static constexpr int SLOT_B   = 576;
static constexpr int COPYO_OFF = 288;
static constexpr int A_BUF    = 24 * SLOT_B;         // 13824
static constexpr int B_OFF    = 2 * A_BUF;           // 27648
static constexpr int B_SLAB   = 8192;
static constexpr int RED_OFF  = B_OFF + 3 * B_SLAB;  // 52224
static constexpr int SMEM_TOTAL = RED_OFF + 2048;    // 54272

__device__ __half x16g[33554432];    // flat fp16 image (even pairs)
__device__ __half x16pE[37748736];   // padded rows, stride 144 (odd pairs)
__device__ __half W2h[24 * 4096];

__device__ __forceinline__ uint32_t smem_u32(const void* p) {
    uint32_t a;
    asm("{ .reg .u64 t; cvta.to.shared.u64 t, %1; cvt.u32.u64 %0, t; }" : "=r"(a) : "l"(p));
    return a;
}
__device__ __forceinline__ uint32_t lds32(uint32_t a) {
    uint32_t v;
    asm volatile("ld.shared.b32 %0, [%1];" : "=r"(v) : "r"(a));
    return v;
}
__device__ __forceinline__ void mma_f16(float& d0, float& d1, float& d2, float& d3,
                                        uint32_t a0, uint32_t a1, uint32_t a2, uint32_t a3,
                                        uint32_t b0, uint32_t b1) {
    asm volatile(
        "mma.sync.aligned.m16n8k16.row.col.f32.f16.f16.f32 "
        "{%0,%1,%2,%3}, {%4,%5,%6,%7}, {%8,%9}, {%0,%1,%2,%3};"
        : "+f"(d0), "+f"(d1), "+f"(d2), "+f"(d3)
        : "r"(a0), "r"(a1), "r"(a2), "r"(a3), "r"(b0), "r"(b1));
}

// ---- pre-kernel 1a: x -> x16g (flat fp16, RNA) ----
__global__ void xeven_kernel(const float* __restrict__ x) {
    int i = blockIdx.x * TPB + threadIdx.x;          // 8-px group
    const float4* s4 = reinterpret_cast<const float4*>(x + (size_t)i * 8);
    float4 v0 = s4[0], v1 = s4[1];
    __half2 p0 = __floats2half2_rn(v0.x, v0.y);
    __half2 p1 = __floats2half2_rn(v0.z, v0.w);
    __half2 p2 = __floats2half2_rn(v1.x, v1.y);
    __half2 p3 = __floats2half2_rn(v1.z, v1.w);
    uint4 u;
    u.x = *reinterpret_cast<uint32_t*>(&p0);
    u.y = *reinterpret_cast<uint32_t*>(&p1);
    u.z = *reinterpret_cast<uint32_t*>(&p2);
    u.w = *reinterpret_cast<uint32_t*>(&p3);
    reinterpret_cast<uint4*>(x16g)[i] = u;
}

// ---- pre-kernel 1b: x -> x16pE (padded rows: [0, x0..x127, 0, 0...]) ----
__global__ void xodd_kernel(const float* __restrict__ x) {
    int idx = blockIdx.x * TPB + threadIdx.x;        // row*18 + chunk
    int row = idx / 18, c = idx - row * 18;
    const float* xr = x + (size_t)row * 128;
    float v[8];
#pragma unroll
    for (int e = 0; e < 8; ++e) {
        int m = 8 * c + e;
        v[e] = (m >= 1 && m <= 128) ? xr[m - 1] : 0.0f;
    }
    __half2 p0 = __floats2half2_rn(v[0], v[1]);
    __half2 p1 = __floats2half2_rn(v[2], v[3]);
    __half2 p2 = __floats2half2_rn(v[4], v[5]);
    __half2 p3 = __floats2half2_rn(v[6], v[7]);
    uint4 u;
    u.x = *reinterpret_cast<uint32_t*>(&p0);
    u.y = *reinterpret_cast<uint32_t*>(&p1);
    u.z = *reinterpret_cast<uint32_t*>(&p2);
    u.w = *reinterpret_cast<uint32_t*>(&p3);
    *reinterpret_cast<uint4*>(x16pE + (size_t)row * 144 + 8 * c) = u;
}

// ---- pre-kernel 2: W (OIHW) -> fragment-ordered fp16 W2h, phantom slot = 0 ----
__global__ void wxform_kernel(const float* __restrict__ Wt) {
    int f = blockIdx.x * TPB + threadIdx.x;
    if (f >= 24 * 4096) return;
    int c = f >> 12, r = f & 4095;
    int unit = r >> 3, h = r & 7;
    int lane = unit & 31, rest = unit >> 5;
    int s = rest >> 3, wn = (rest & 7) >> 1, j = rest & 1;
    int word = h >> 1, hw = h & 1;
    int nt = wn * 4 + j * 2 + (word >> 1);
    int breg = word & 1;
    int t = lane & 3, q = lane >> 2;
    int oc = nt * 8 + q;
    int k  = 2 * t + hw + 8 * breg + 16 * s;
    int icl = k >> 2, kxs = k & 3;
    int c3 = c / 3, ic0 = c3 * 8, ky = c - 3 * c3;
    float v = (kxs < 3) ? Wt[oc * 576 + (ic0 + icl) * 9 + ky * 3 + kxs] : 0.0f;
    W2h[f] = __float2half_rn(v);
}

__global__ void __launch_bounds__(TPB, 2)
conv_min_mma9_kernel(float* __restrict__ out)
{
    extern __shared__ char smem[];
    const uint32_t sb = smem_u32(smem);
    const int tid    = threadIdx.x;
    const int lane   = tid & 31;
    const int wid    = tid >> 5;
    const int warp_m = wid >> 2;   // 0..1
    const int warp_n = wid & 3;    // 0..3
    const int q = lane >> 2;
    const int t = lane & 3;
    const int y = blockIdx.x;
    const int b = blockIdx.y;

    // ---- zero slot pads [544,576) for all 48 slot instances ----
    for (int w = tid; w < 384; w += TPB) {
        int sl = w >> 3, pw = w & 7;
        asm volatile("st.shared.b32 [%0], %1;"
                     :: "r"(sb + (uint32_t)(sl * SLOT_B + 544 + pw * 4)), "r"(0u)
                     : "memory");
    }

    // ---- per-lane A-gather base ----
    const int sW = warp_m * 64 + q + ((t & 1) ? 1 : -1);
    const uint32_t parOff = (sW & 1) ? (uint32_t)(((sW + 1) >> 1) * 4)
                                     : (uint32_t)(COPYO_OFF + (sW >> 1) * 4);
    const uint32_t laneA = (uint32_t)((t >> 1) * 1728) + parOff;

    // ---- per-thread A-fill descriptors (4 rounds, 33 chunks/slot) ----
    const __half* f_ptr[4];
    uint32_t f_dst[4];
    int f_gstr[4];
    bool f_val[4], f_ok[4];
#pragma unroll
    for (int i = 0; i < 4; ++i) {
        int ch = tid + TPB * i;
        f_val[i] = (ch < 792);
        int chc = f_val[i] ? ch : 0;
        int slot = chc / 33, w = chc - slot * 33;
        int icl = slot / 3, kyr = slot - icl * 3;
        int gy = y + kyr - 1;
        f_ok[i] = f_val[i] && ((unsigned)gy < 128u);
        if (w < 17) {
            f_dst[i]  = (uint32_t)(slot * SLOT_B + w * 16);
            f_ptr[i]  = x16pE + ((size_t)b * 1179648 + icl * 18432 +
                                 (size_t)gy * 144 + w * 8);
            f_gstr[i] = 147456;
        } else {
            f_dst[i]  = (uint32_t)(slot * SLOT_B + COPYO_OFF + (w - 17) * 16);
            f_ptr[i]  = x16g + ((size_t)b * 1048576 + icl * 16384 +
                                (size_t)gy * 128 + (w - 17) * 8);
            f_gstr[i] = 131072;
        }
        if (!f_ok[i]) f_ptr[i] = x16g;   // safe src for sz=0
    }

    float acc[4][4][4];
#pragma unroll
    for (int mt = 0; mt < 4; ++mt)
#pragma unroll
        for (int nt = 0; nt < 4; ++nt)
#pragma unroll
            for (int r = 0; r < 4; ++r) acc[mt][nt][r] = 0.0f;

    __syncthreads();

    // ---- prologue: commit rows(g0), B(0), B(1) ----
#pragma unroll
    for (int i = 0; i < 4; ++i) {
        if (f_val[i]) {
            uint32_t sz = f_ok[i] ? 16u : 0u;
            uint64_t g64 = __cvta_generic_to_global((const void*)f_ptr[i]);
            asm volatile("cp.async.cg.shared.global [%0], [%1], 16, %2;"
                         :: "r"(sb + f_dst[i]), "l"(g64), "r"(sz) : "memory");
        }
    }
    asm volatile("cp.async.commit_group;" ::: "memory");
#pragma unroll
    for (int cc = 0; cc < 2; ++cc) {
        uint32_t dst = sb + B_OFF + cc * B_SLAB;
        const __half* src = W2h + cc * 4096;
#pragma unroll
        for (int i = 0; i < 2; ++i) {
            int j = tid + TPB * i;
            uint64_t g64 = __cvta_generic_to_global((const void*)(src + j * 8));
            asm volatile("cp.async.cg.shared.global [%0], [%1], 16;"
                         :: "r"(dst + (uint32_t)(j * 16)), "l"(g64) : "memory");
        }
        asm volatile("cp.async.commit_group;" ::: "memory");
    }

    int g = 0, kyc = 0;
#pragma unroll 1
    for (int c = 0; c < 24; ++c) {
        asm volatile("cp.async.wait_group 1;" ::: "memory");
        __syncthreads();

        // first chunk of ic-group: issue rows for group g+1 (opposite buffer)
        if (kyc == 0 && g < 7) {
            uint32_t pb = sb + (uint32_t)(((g + 1) & 1) * A_BUF);
            int g1 = g + 1;
#pragma unroll
            for (int i = 0; i < 4; ++i) {
                if (f_val[i]) {
                    const __half* sp = f_ok[i] ? (f_ptr[i] + (size_t)g1 * f_gstr[i])
                                               : x16g;
                    uint32_t sz = f_ok[i] ? 16u : 0u;
                    uint64_t g64 = __cvta_generic_to_global((const void*)sp);
                    asm volatile("cp.async.cg.shared.global [%0], [%1], 16, %2;"
                                 :: "r"(pb + f_dst[i]), "l"(g64), "r"(sz) : "memory");
                }
            }
        }
        // issue B(c+2)
        if (c + 2 < 24) {
            uint32_t dst = sb + B_OFF + (uint32_t)((c + 2) % 3) * B_SLAB;
            const __half* src = W2h + (c + 2) * 4096;
#pragma unroll
            for (int i = 0; i < 2; ++i) {
                int j = tid + TPB * i;
                uint64_t g64 = __cvta_generic_to_global((const void*)(src + j * 8));
                asm volatile("cp.async.cg.shared.global [%0], [%1], 16;"
                             :: "r"(dst + (uint32_t)(j * 16)), "l"(g64) : "memory");
            }
        }
        asm volatile("cp.async.commit_group;" ::: "memory");

        // ---- compute chunk c: 2 k16-steps ----
        const uint32_t aBase = sb + (uint32_t)((g & 1) * A_BUF + kyc * SLOT_B) + laneA;
        const uint32_t bBase = sb + B_OFF + (uint32_t)(c % 3) * B_SLAB +
                               (uint32_t)(warp_n * 1024 + lane * 16);
#pragma unroll
        for (int s = 0; s < 2; ++s) {
            const uint32_t aS = aBase + (uint32_t)(s * 6912);
            uint32_t a0[4], a1[4], a2[4], a3[4];
#pragma unroll
            for (int mt = 0; mt < 4; ++mt) {
                a0[mt] = lds32(aS + (uint32_t)(mt * 32));
                a1[mt] = lds32(aS + (uint32_t)(mt * 32 + 16));
                a2[mt] = lds32(aS + (uint32_t)(mt * 32 + 3456));
                a3[mt] = lds32(aS + (uint32_t)(mt * 32 + 3472));
            }
            uint32_t b0[4], b1[4];
#pragma unroll
            for (int j = 0; j < 2; ++j) {
                uint32_t addr = bBase + (uint32_t)(s * 4096 + j * 512);
                asm volatile("ld.shared.v4.b32 {%0,%1,%2,%3}, [%4];"
                             : "=r"(b0[2 * j]), "=r"(b1[2 * j]),
                               "=r"(b0[2 * j + 1]), "=r"(b1[2 * j + 1])
                             : "r"(addr));
            }
#pragma unroll
            for (int mt = 0; mt < 4; ++mt)
#pragma unroll
                for (int nt = 0; nt < 4; ++nt)
                    mma_f16(acc[mt][nt][0], acc[mt][nt][1],
                            acc[mt][nt][2], acc[mt][nt][3],
                            a0[mt], a1[mt], a2[mt], a3[mt], b0[nt], b1[nt]);
        }

        if (++kyc == 3) { kyc = 0; ++g; }
    }

    // ---- epilogue: min over oc, *2, write ----
    float rmin[4][2];
#pragma unroll
    for (int mt = 0; mt < 4; ++mt) {
        float lo = fminf(acc[mt][0][0], acc[mt][0][1]);
        float hi = fminf(acc[mt][0][2], acc[mt][0][3]);
#pragma unroll
        for (int nt = 1; nt < 4; ++nt) {
            lo = fminf(lo, fminf(acc[mt][nt][0], acc[mt][nt][1]));
            hi = fminf(hi, fminf(acc[mt][nt][2], acc[mt][nt][3]));
        }
        rmin[mt][0] = lo;
        rmin[mt][1] = hi;
    }
#pragma unroll
    for (int d = 1; d <= 2; d <<= 1)
#pragma unroll
        for (int mt = 0; mt < 4; ++mt)
#pragma unroll
            for (int h = 0; h < 2; ++h)
                rmin[mt][h] = fminf(rmin[mt][h],
                                    __shfl_xor_sync(0xffffffffu, rmin[mt][h], d));

    float* red = reinterpret_cast<float*>(smem + RED_OFF);
    __syncthreads();
    if ((lane & 3) == 0) {
        int gq = lane >> 2;
#pragma unroll
        for (int mt = 0; mt < 4; ++mt)
#pragma unroll
            for (int h = 0; h < 2; ++h) {
                int row = (warp_m * 4 + mt) * 16 + h * 8 + gq;
                red[row * 4 + warp_n] = rmin[mt][h];
            }
    }
    __syncthreads();
    if (tid < 128) {
        float m = fminf(fminf(red[tid * 4 + 0], red[tid * 4 + 1]),
                        fminf(red[tid * 4 + 2], red[tid * 4 + 3]));
        out[(size_t)b * 16384 + y * 128 + tid] = m * 2.0f;
    }
}

extern "C" void kernel_launch(void* const* d_in, const int* in_sizes, int n_in,
                              void* d_out, int out_size)
{
    const float* x  = (const float*)d_in[0];
    const float* Wt = (const float*)d_in[1];
    float* out = (float*)d_out;

    cudaFuncSetAttribute(conv_min_mma9_kernel,
                         cudaFuncAttributeMaxDynamicSharedMemorySize, SMEM_TOTAL);

    xeven_kernel<<<16384, TPB>>>(x);
    xodd_kernel<<<18432, TPB>>>(x);
    wxform_kernel<<<(24 * 4096 + TPB - 1) / TPB, TPB>>>(Wt);

    dim3 grid(128, 32);   // rows x batch
    conv_min_mma9_kernel<<<grid, TPB, SMEM_TOTAL>>>(out);
}

// round 13
// speedup vs baseline: 2.8511x; 1.5193x over previous
#include <cuda_runtime.h>
#include <cuda_fp16.h>
#include <cstdint>
#include <cfloat>

// Fused conv2d 3x3 SAME -> min over C_out -> *2 via pipelined mma.sync FP16
// (m16n8k16, f32 accumulate). x:(32,64,128,128) f32, W:(128,64,3,3) f32.
//
// Round 13 = R12 with the fp16 k-pair moved from the pixel axis to the IC axis:
//  - pre-kernel builds an ic-interleaved padded image x16i: plane ip = ic/2,
//    row = [0, (x[2ip],x[2ip+1]) for px 0..127, 0, pad] (136 half2 words)
//  - k16 step = 16 real ics at fixed (ky,kx); kx = word offset in the gather
//    -> NO phantom K: 576 K = 36 k16 steps (was 48) -> tensor floor ~127us
//  - chunk = (16 ic, 1 ky) = 3 k16-steps (kx=0,1,2), 12 chunks
//  - A slab: 24 slots (3 ky x 8 ip-planes) x 544B, filled once per ic-group,
//    reused by all 9 taps; gathers provably 1-wavefront (banks 8t+q distinct)

#define TPB 256

static constexpr int SLOT_B = 544;                  // 136 half2 words
static constexpr int A_BUF  = 24 * SLOT_B;          // 13056
static constexpr int B_OFF  = 2 * A_BUF;            // 26112
static constexpr int B_SLAB = 12288;                // 3 steps x 4096
static constexpr int RED_OFF = B_OFF + 3 * B_SLAB;  // 62976
static constexpr int SMEM_TOTAL = RED_OFF + 2048;   // 65024

static constexpr int IMG_ROW   = 272;               // halves per padded row
static constexpr int ICG_STRH  = 8 * 128 * IMG_ROW; // 278528 halves per 8-plane group

__device__ __half x16i[35651584];   // 32 b x 32 planes x 128 rows x 272 halves
__device__ __half W2h[12 * 6144];

__device__ __forceinline__ uint32_t smem_u32(const void* p) {
    uint32_t a;
    asm("{ .reg .u64 t; cvta.to.shared.u64 t, %1; cvt.u32.u64 %0, t; }" : "=r"(a) : "l"(p));
    return a;
}
__device__ __forceinline__ uint32_t lds32(uint32_t a) {
    uint32_t v;
    asm volatile("ld.shared.b32 %0, [%1];" : "=r"(v) : "r"(a));
    return v;
}
__device__ __forceinline__ void mma_f16(float& d0, float& d1, float& d2, float& d3,
                                        uint32_t a0, uint32_t a1, uint32_t a2, uint32_t a3,
                                        uint32_t b0, uint32_t b1) {
    asm volatile(
        "mma.sync.aligned.m16n8k16.row.col.f32.f16.f16.f32 "
        "{%0,%1,%2,%3}, {%4,%5,%6,%7}, {%8,%9}, {%0,%1,%2,%3};"
        : "+f"(d0), "+f"(d1), "+f"(d2), "+f"(d3)
        : "r"(a0), "r"(a1), "r"(a2), "r"(a3), "r"(b0), "r"(b1));
}

// ---- pre-kernel 1: x -> ic-interleaved padded fp16 image ----
// word wi of row (b, plane p, gy): c = wi-1; (x[2p][gy][c], x[2p+1][gy][c]) or 0
__global__ void xi_kernel(const float* __restrict__ x) {
    int idx = blockIdx.x * TPB + threadIdx.x;       // 16B chunk = 4 words
    int w4 = idx % 34;
    int rr = idx / 34;
    int gy = rr & 127;
    int rr2 = rr >> 7;
    int p = rr2 & 31;
    int b = rr2 >> 5;
    const float* s0 = x + ((size_t)(b * 64 + 2 * p) * 128 + gy) * 128;
    const float* s1 = s0 + 16384;
    uint32_t w[4];
#pragma unroll
    for (int j = 0; j < 4; ++j) {
        int c = w4 * 4 + j - 1;
        float lo = 0.f, hi = 0.f;
        if ((unsigned)c < 128u) { lo = s0[c]; hi = s1[c]; }
        __half2 h = __floats2half2_rn(lo, hi);
        w[j] = *reinterpret_cast<uint32_t*>(&h);
    }
    uint4 u = make_uint4(w[0], w[1], w[2], w[3]);
    size_t off = ((size_t)(b * 32 + p) * 128 + gy) * IMG_ROW + (size_t)w4 * 8;
    *reinterpret_cast<uint4*>(x16i + off) = u;
}

// ---- pre-kernel 2: W -> fragment-ordered fp16 W2h (no phantom) ----
// chunk c: icg = c/3, ky = c%3. unit16 = (s*8 + warp_n*2 + j)*32 + lane;
// half h: word = h>>1, hw = h&1; nt = wn*4 + j*2 + (word>>1); breg = word&1
// t = lane&3, q = lane>>2: oc = nt*8+q; ipl = t + 4*breg; ic = icg*16 + ipl*2 + hw
__global__ void wxform_kernel(const float* __restrict__ Wt) {
    int f = blockIdx.x * TPB + threadIdx.x;
    if (f >= 12 * 6144) return;
    int c = f / 6144;
    int r = f - c * 6144;
    int unit = r >> 3, h = r & 7;
    int lane = unit & 31, rest = unit >> 5;       // rest 0..23
    int s  = rest >> 3;                           // kx
    int wn = (rest >> 1) & 3;
    int j  = rest & 1;
    int word = h >> 1, hw = h & 1;
    int nt = wn * 4 + j * 2 + (word >> 1);
    int breg = word & 1;
    int t = lane & 3, q = lane >> 2;
    int oc  = nt * 8 + q;
    int ipl = t + 4 * breg;
    int icg = c / 3, ky = c - 3 * icg;
    int ic  = icg * 16 + ipl * 2 + hw;
    W2h[f] = __float2half_rn(Wt[oc * 576 + ic * 9 + ky * 3 + s]);
}

__global__ void __launch_bounds__(TPB, 2)
conv_min_mma10_kernel(float* __restrict__ out)
{
    extern __shared__ char smem[];
    const uint32_t sb = smem_u32(smem);
    const int tid    = threadIdx.x;
    const int lane   = tid & 31;
    const int wid    = tid >> 5;
    const int warp_m = wid >> 2;   // 0..1
    const int warp_n = wid & 3;    // 0..3
    const int q = lane >> 2;
    const int t = lane & 3;
    const int y = blockIdx.x;
    const int b = blockIdx.y;

    // per-lane A gather base: slot(kyc*8 + t), word (warp_m*64 + q) + kx
    const uint32_t laneA = (uint32_t)(t * SLOT_B + (warp_m * 64 + q) * 4);

    // ---- per-thread A-fill descriptors: 816 16B-chunks per ic-group ----
    const __half* f_src[4];
    uint32_t f_dst[4];
    bool f_ok[4], f_val[4];
#pragma unroll
    for (int i = 0; i < 4; ++i) {
        int ch = tid + TPB * i;
        f_val[i] = (ch < 816);
        int chc  = f_val[i] ? ch : 0;
        int slot = chc / 34, w4 = chc - slot * 34;
        int kyr = slot >> 3, ipl = slot & 7;
        int gy = y + kyr - 1;
        f_ok[i]  = f_val[i] && ((unsigned)gy < 128u);
        f_dst[i] = (uint32_t)(slot * SLOT_B + w4 * 16);
        f_src[i] = f_ok[i]
            ? x16i + (((size_t)(b * 32 + ipl) * 128 + gy) * IMG_ROW + (size_t)w4 * 8)
            : x16i;
    }

    float acc[4][4][4];
#pragma unroll
    for (int mt = 0; mt < 4; ++mt)
#pragma unroll
        for (int nt = 0; nt < 4; ++nt)
#pragma unroll
            for (int r = 0; r < 4; ++r) acc[mt][nt][r] = 0.0f;

    // ---- prologue: commit A(icg0); B(0); B(1) ----
#pragma unroll
    for (int i = 0; i < 4; ++i) {
        if (f_val[i]) {
            uint32_t sz = f_ok[i] ? 16u : 0u;
            uint64_t g64 = __cvta_generic_to_global((const void*)f_src[i]);
            asm volatile("cp.async.cg.shared.global [%0], [%1], 16, %2;"
                         :: "r"(sb + f_dst[i]), "l"(g64), "r"(sz) : "memory");
        }
    }
    asm volatile("cp.async.commit_group;" ::: "memory");
#pragma unroll
    for (int cc = 0; cc < 2; ++cc) {
        uint32_t dst = sb + B_OFF + cc * B_SLAB;
        const __half* src = W2h + cc * 6144;
#pragma unroll
        for (int i = 0; i < 3; ++i) {
            int j = tid + TPB * i;
            uint64_t g64 = __cvta_generic_to_global((const void*)(src + j * 8));
            asm volatile("cp.async.cg.shared.global [%0], [%1], 16;"
                         :: "r"(dst + (uint32_t)(j * 16)), "l"(g64) : "memory");
        }
        asm volatile("cp.async.commit_group;" ::: "memory");
    }

    int icg = 0, kyc = 0;
#pragma unroll 1
    for (int c = 0; c < 12; ++c) {
        asm volatile("cp.async.wait_group 1;" ::: "memory");
        __syncthreads();

        // first chunk of ic-group: issue A rows for icg+1 (opposite buffer)
        if (kyc == 0 && icg < 3) {
            uint32_t pb = sb + (uint32_t)(((icg + 1) & 1) * A_BUF);
            size_t adv = (size_t)(icg + 1) * ICG_STRH;
#pragma unroll
            for (int i = 0; i < 4; ++i) {
                if (f_val[i]) {
                    const __half* sp = f_ok[i] ? (f_src[i] + adv) : x16i;
                    uint32_t sz = f_ok[i] ? 16u : 0u;
                    uint64_t g64 = __cvta_generic_to_global((const void*)sp);
                    asm volatile("cp.async.cg.shared.global [%0], [%1], 16, %2;"
                                 :: "r"(pb + f_dst[i]), "l"(g64), "r"(sz) : "memory");
                }
            }
        }
        // issue B(c+2)
        if (c + 2 < 12) {
            uint32_t dst = sb + B_OFF + (uint32_t)((c + 2) % 3) * B_SLAB;
            const __half* src = W2h + (c + 2) * 6144;
#pragma unroll
            for (int i = 0; i < 3; ++i) {
                int j = tid + TPB * i;
                uint64_t g64 = __cvta_generic_to_global((const void*)(src + j * 8));
                asm volatile("cp.async.cg.shared.global [%0], [%1], 16;"
                             :: "r"(dst + (uint32_t)(j * 16)), "l"(g64) : "memory");
            }
        }
        asm volatile("cp.async.commit_group;" ::: "memory");

        // ---- compute chunk c: 3 k16-steps (kx = 0,1,2) ----
        const uint32_t aBase = sb + (uint32_t)((icg & 1) * A_BUF + kyc * (8 * SLOT_B))
                               + laneA;
        const uint32_t bBase = sb + B_OFF + (uint32_t)(c % 3) * B_SLAB +
                               (uint32_t)(warp_n * 1024 + lane * 16);
#pragma unroll
        for (int s = 0; s < 3; ++s) {
            const uint32_t aS = aBase + (uint32_t)(s * 4);
            uint32_t a0[4], a1[4], a2[4], a3[4];
#pragma unroll
            for (int mt = 0; mt < 4; ++mt) {
                uint32_t base = aS + (uint32_t)(mt * 64);
                a0[mt] = lds32(base);
                a1[mt] = lds32(base + 32);
                a2[mt] = lds32(base + 4 * SLOT_B);
                a3[mt] = lds32(base + 4 * SLOT_B + 32);
            }
            uint32_t b0[4], b1[4];
#pragma unroll
            for (int j = 0; j < 2; ++j) {
                uint32_t addr = bBase + (uint32_t)(s * 4096 + j * 512);
                asm volatile("ld.shared.v4.b32 {%0,%1,%2,%3}, [%4];"
                             : "=r"(b0[2 * j]), "=r"(b1[2 * j]),
                               "=r"(b0[2 * j + 1]), "=r"(b1[2 * j + 1])
                             : "r"(addr));
            }
#pragma unroll
            for (int mt = 0; mt < 4; ++mt)
#pragma unroll
                for (int nt = 0; nt < 4; ++nt)
                    mma_f16(acc[mt][nt][0], acc[mt][nt][1],
                            acc[mt][nt][2], acc[mt][nt][3],
                            a0[mt], a1[mt], a2[mt], a3[mt], b0[nt], b1[nt]);
        }

        if (++kyc == 3) { kyc = 0; ++icg; }
    }

    // ---- epilogue: min over oc, *2, write ----
    float rmin[4][2];
#pragma unroll
    for (int mt = 0; mt < 4; ++mt) {
        float lo = fminf(acc[mt][0][0], acc[mt][0][1]);
        float hi = fminf(acc[mt][0][2], acc[mt][0][3]);
#pragma unroll
        for (int nt = 1; nt < 4; ++nt) {
            lo = fminf(lo, fminf(acc[mt][nt][0], acc[mt][nt][1]));
            hi = fminf(hi, fminf(acc[mt][nt][2], acc[mt][nt][3]));
        }
        rmin[mt][0] = lo;
        rmin[mt][1] = hi;
    }
#pragma unroll
    for (int d = 1; d <= 2; d <<= 1)
#pragma unroll
        for (int mt = 0; mt < 4; ++mt)
#pragma unroll
            for (int h = 0; h < 2; ++h)
                rmin[mt][h] = fminf(rmin[mt][h],
                                    __shfl_xor_sync(0xffffffffu, rmin[mt][h], d));

    float* red = reinterpret_cast<float*>(smem + RED_OFF);
    __syncthreads();
    if ((lane & 3) == 0) {
        int gq = lane >> 2;
#pragma unroll
        for (int mt = 0; mt < 4; ++mt)
#pragma unroll
            for (int h = 0; h < 2; ++h) {
                int row = (warp_m * 4 + mt) * 16 + h * 8 + gq;
                red[row * 4 + warp_n] = rmin[mt][h];
            }
    }
    __syncthreads();
    if (tid < 128) {
        float m = fminf(fminf(red[tid * 4 + 0], red[tid * 4 + 1]),
                        fminf(red[tid * 4 + 2], red[tid * 4 + 3]));
        out[(size_t)b * 16384 + y * 128 + tid] = m * 2.0f;
    }
}

extern "C" void kernel_launch(void* const* d_in, const int* in_sizes, int n_in,
                              void* d_out, int out_size)
{
    const float* x  = (const float*)d_in[0];
    const float* Wt = (const float*)d_in[1];
    float* out = (float*)d_out;

    cudaFuncSetAttribute(conv_min_mma10_kernel,
                         cudaFuncAttributeMaxDynamicSharedMemorySize, SMEM_TOTAL);

    xi_kernel<<<17408, TPB>>>(x);                           // 32*32*128*34 / 256
    wxform_kernel<<<(12 * 6144 + TPB - 1) / TPB, TPB>>>(Wt);

    dim3 grid(128, 32);   // rows x batch
    conv_min_mma10_kernel<<<grid, TPB, SMEM_TOTAL>>>(out);
}

// round 14
// speedup vs baseline: 3.0827x; 1.0812x over previous
#include <cuda_runtime.h>
#include <cuda_fp16.h>
#include <cstdint>
#include <cfloat>

// Fused conv2d 3x3 SAME -> min over C_out -> *2 via pipelined mma.sync FP16
// (m16n8k16, f32 accumulate). x:(32,64,128,128) f32, W:(128,64,3,3) f32.
//
// Round 14 = R13 with the 3 ky-chunks of an ic-group merged into ONE chunk:
//  - chunk = (16 ic x 3 ky x 3 kx) = 9 k16-steps; 4 chunks total
//  - B double-buffered at 36.9KB/slab (2-stage); A parity buffers as before
//  - one wait_group + 2 syncs per chunk (prefetch issued after compute)
//  - everything else (ic-interleaved padded image, gathers, epilogue) = R13

#define TPB 256

static constexpr int SLOT_B = 544;                  // 136 half2 words
static constexpr int A_BUF  = 24 * SLOT_B;          // 13056 (3 ky x 8 planes)
static constexpr int B_OFF  = 2 * A_BUF;            // 26112
static constexpr int B_SLAB = 9 * 4096;             // 36864
static constexpr int RED_OFF = B_OFF + 2 * B_SLAB;  // 99840
static constexpr int SMEM_TOTAL = RED_OFF + 2048;   // 101888 (2 CTA/SM)

static constexpr int IMG_ROW  = 272;                // halves per padded row
static constexpr int ICG_STRH = 8 * 128 * IMG_ROW;  // halves per 8-plane group

__device__ __half x16i[35651584];   // 32 b x 32 planes x 128 rows x 272 halves
__device__ __half W2h[4 * 18432];

__device__ __forceinline__ uint32_t smem_u32(const void* p) {
    uint32_t a;
    asm("{ .reg .u64 t; cvta.to.shared.u64 t, %1; cvt.u32.u64 %0, t; }" : "=r"(a) : "l"(p));
    return a;
}
__device__ __forceinline__ uint32_t lds32(uint32_t a) {
    uint32_t v;
    asm volatile("ld.shared.b32 %0, [%1];" : "=r"(v) : "r"(a));
    return v;
}
__device__ __forceinline__ void mma_f16(float& d0, float& d1, float& d2, float& d3,
                                        uint32_t a0, uint32_t a1, uint32_t a2, uint32_t a3,
                                        uint32_t b0, uint32_t b1) {
    asm volatile(
        "mma.sync.aligned.m16n8k16.row.col.f32.f16.f16.f32 "
        "{%0,%1,%2,%3}, {%4,%5,%6,%7}, {%8,%9}, {%0,%1,%2,%3};"
        : "+f"(d0), "+f"(d1), "+f"(d2), "+f"(d3)
        : "r"(a0), "r"(a1), "r"(a2), "r"(a3), "r"(b0), "r"(b1));
}

// ---- pre-kernel 1: x -> ic-interleaved padded fp16 image (as R13) ----
__global__ void xi_kernel(const float* __restrict__ x) {
    int idx = blockIdx.x * TPB + threadIdx.x;       // 16B chunk = 4 words
    int w4 = idx % 34;
    int rr = idx / 34;
    int gy = rr & 127;
    int rr2 = rr >> 7;
    int p = rr2 & 31;
    int b = rr2 >> 5;
    const float* s0 = x + ((size_t)(b * 64 + 2 * p) * 128 + gy) * 128;
    const float* s1 = s0 + 16384;
    uint32_t w[4];
#pragma unroll
    for (int j = 0; j < 4; ++j) {
        int c = w4 * 4 + j - 1;
        float lo = 0.f, hi = 0.f;
        if ((unsigned)c < 128u) { lo = s0[c]; hi = s1[c]; }
        __half2 h = __floats2half2_rn(lo, hi);
        w[j] = *reinterpret_cast<uint32_t*>(&h);
    }
    uint4 u = make_uint4(w[0], w[1], w[2], w[3]);
    size_t off = ((size_t)(b * 32 + p) * 128 + gy) * IMG_ROW + (size_t)w4 * 8;
    *reinterpret_cast<uint4*>(x16i + off) = u;
}

// ---- pre-kernel 2: W -> fragment-ordered fp16 W2h, 4 chunks x 9 steps ----
// f: c = f/18432; r = f%18432; st = r/2048 (ky=st/3, kx=st%3); u = r%2048;
// unit = u>>3: lane = unit&31, rest = unit>>5 (0..7): wn = rest>>1, j = rest&1
// h = u&7: word = h>>1, hw = h&1; nt = wn*4 + j*2 + (word>>1); breg = word&1
// t = lane&3, q = lane>>2: oc = nt*8+q; ipl = t+4*breg; ic = c*16 + ipl*2 + hw
__global__ void wxform_kernel(const float* __restrict__ Wt) {
    int f = blockIdx.x * TPB + threadIdx.x;
    if (f >= 4 * 18432) return;
    int c = f / 18432;
    int r = f - c * 18432;
    int st = r >> 11;
    int u  = r & 2047;
    int ky = st / 3, kx = st - 3 * ky;
    int unit = u >> 3, h = u & 7;
    int lane = unit & 31, rest = unit >> 5;
    int wn = rest >> 1, j = rest & 1;
    int word = h >> 1, hw = h & 1;
    int nt = wn * 4 + j * 2 + (word >> 1);
    int breg = word & 1;
    int t = lane & 3, q = lane >> 2;
    int oc  = nt * 8 + q;
    int ipl = t + 4 * breg;
    int ic  = c * 16 + ipl * 2 + hw;
    W2h[f] = __float2half_rn(Wt[oc * 576 + ic * 9 + ky * 3 + kx]);
}

__global__ void __launch_bounds__(TPB, 2)
conv_min_mma11_kernel(float* __restrict__ out)
{
    extern __shared__ char smem[];
    const uint32_t sb = smem_u32(smem);
    const int tid    = threadIdx.x;
    const int lane   = tid & 31;
    const int wid    = tid >> 5;
    const int warp_m = wid >> 2;   // 0..1
    const int warp_n = wid & 3;    // 0..3
    const int q = lane >> 2;
    const int t = lane & 3;
    const int y = blockIdx.x;
    const int b = blockIdx.y;

    // per-lane A gather base: plane slot t, word (warp_m*64 + q)
    const uint32_t laneA = (uint32_t)(t * SLOT_B + (warp_m * 64 + q) * 4);

    // ---- per-thread A-fill descriptors: 816 16B-chunks per chunk (ic-group) ----
    const __half* f_src[4];
    uint32_t f_dst[4];
    bool f_ok[4], f_val[4];
#pragma unroll
    for (int i = 0; i < 4; ++i) {
        int ch = tid + TPB * i;
        f_val[i] = (ch < 816);
        int chc  = f_val[i] ? ch : 0;
        int slot = chc / 34, w4 = chc - slot * 34;
        int kyr = slot >> 3, ipl = slot & 7;
        int gy = y + kyr - 1;
        f_ok[i]  = f_val[i] && ((unsigned)gy < 128u);
        f_dst[i] = (uint32_t)(slot * SLOT_B + w4 * 16);
        f_src[i] = f_ok[i]
            ? x16i + (((size_t)(b * 32 + ipl) * 128 + gy) * IMG_ROW + (size_t)w4 * 8)
            : x16i;
    }

    float acc[4][4][4];
#pragma unroll
    for (int mt = 0; mt < 4; ++mt)
#pragma unroll
        for (int nt = 0; nt < 4; ++nt)
#pragma unroll
            for (int r = 0; r < 4; ++r) acc[mt][nt][r] = 0.0f;

    // ---- prologue: group0 = A(0)+B(0); group1 = A(1)+B(1) ----
#pragma unroll
    for (int cc = 0; cc < 2; ++cc) {
        size_t adv = (size_t)cc * ICG_STRH;
        uint32_t ab = sb + (uint32_t)(cc * A_BUF);
#pragma unroll
        for (int i = 0; i < 4; ++i) {
            if (f_val[i]) {
                const __half* sp = f_ok[i] ? (f_src[i] + adv) : x16i;
                uint32_t sz = f_ok[i] ? 16u : 0u;
                uint64_t g64 = __cvta_generic_to_global((const void*)sp);
                asm volatile("cp.async.cg.shared.global [%0], [%1], 16, %2;"
                             :: "r"(ab + f_dst[i]), "l"(g64), "r"(sz) : "memory");
            }
        }
        uint32_t bdst = sb + B_OFF + (uint32_t)(cc * B_SLAB);
        const __half* bsrc = W2h + cc * 18432;
#pragma unroll
        for (int i = 0; i < 9; ++i) {
            int j = tid + TPB * i;
            uint64_t g64 = __cvta_generic_to_global((const void*)(bsrc + j * 8));
            asm volatile("cp.async.cg.shared.global [%0], [%1], 16;"
                         :: "r"(bdst + (uint32_t)(j * 16)), "l"(g64) : "memory");
        }
        asm volatile("cp.async.commit_group;" ::: "memory");
    }

#pragma unroll 1
    for (int c = 0; c < 4; ++c) {
        asm volatile("cp.async.wait_group 1;" ::: "memory");
        __syncthreads();

        // ---- compute chunk c: 9 k16-steps (ky, kx) ----
        const uint32_t aC = sb + (uint32_t)((c & 1) * A_BUF) + laneA;
        const uint32_t bC = sb + B_OFF + (uint32_t)((c & 1) * B_SLAB) +
                            (uint32_t)(warp_n * 1024 + lane * 16);
#pragma unroll
        for (int ky = 0; ky < 3; ++ky) {
#pragma unroll
            for (int kx = 0; kx < 3; ++kx) {
                const uint32_t aS = aC + (uint32_t)(ky * (8 * SLOT_B) + kx * 4);
                const uint32_t bS = bC + (uint32_t)((ky * 3 + kx) * 4096);
                uint32_t a0[4], a1[4], a2[4], a3[4];
#pragma unroll
                for (int mt = 0; mt < 4; ++mt) {
                    uint32_t base = aS + (uint32_t)(mt * 64);
                    a0[mt] = lds32(base);
                    a1[mt] = lds32(base + 32);
                    a2[mt] = lds32(base + 4 * SLOT_B);
                    a3[mt] = lds32(base + 4 * SLOT_B + 32);
                }
                uint32_t b0[4], b1[4];
#pragma unroll
                for (int j = 0; j < 2; ++j) {
                    uint32_t addr = bS + (uint32_t)(j * 512);
                    asm volatile("ld.shared.v4.b32 {%0,%1,%2,%3}, [%4];"
                                 : "=r"(b0[2 * j]), "=r"(b1[2 * j]),
                                   "=r"(b0[2 * j + 1]), "=r"(b1[2 * j + 1])
                                 : "r"(addr));
                }
#pragma unroll
                for (int mt = 0; mt < 4; ++mt)
#pragma unroll
                    for (int nt = 0; nt < 4; ++nt)
                        mma_f16(acc[mt][nt][0], acc[mt][nt][1],
                                acc[mt][nt][2], acc[mt][nt][3],
                                a0[mt], a1[mt], a2[mt], a3[mt], b0[nt], b1[nt]);
            }
        }

        // all warps done reading parity-c buffers -> safe to refill
        __syncthreads();
        if (c + 2 < 4) {
            size_t adv = (size_t)(c + 2) * ICG_STRH;
            uint32_t ab = sb + (uint32_t)((c & 1) * A_BUF);
#pragma unroll
            for (int i = 0; i < 4; ++i) {
                if (f_val[i]) {
                    const __half* sp = f_ok[i] ? (f_src[i] + adv) : x16i;
                    uint32_t sz = f_ok[i] ? 16u : 0u;
                    uint64_t g64 = __cvta_generic_to_global((const void*)sp);
                    asm volatile("cp.async.cg.shared.global [%0], [%1], 16, %2;"
                                 :: "r"(ab + f_dst[i]), "l"(g64), "r"(sz) : "memory");
                }
            }
            uint32_t bdst = sb + B_OFF + (uint32_t)((c & 1) * B_SLAB);
            const __half* bsrc = W2h + (c + 2) * 18432;
#pragma unroll
            for (int i = 0; i < 9; ++i) {
                int j = tid + TPB * i;
                uint64_t g64 = __cvta_generic_to_global((const void*)(bsrc + j * 8));
                asm volatile("cp.async.cg.shared.global [%0], [%1], 16;"
                             :: "r"(bdst + (uint32_t)(j * 16)), "l"(g64) : "memory");
            }
        }
        asm volatile("cp.async.commit_group;" ::: "memory");
    }

    // ---- epilogue: min over oc, *2, write ----
    float rmin[4][2];
#pragma unroll
    for (int mt = 0; mt < 4; ++mt) {
        float lo = fminf(acc[mt][0][0], acc[mt][0][1]);
        float hi = fminf(acc[mt][0][2], acc[mt][0][3]);
#pragma unroll
        for (int nt = 1; nt < 4; ++nt) {
            lo = fminf(lo, fminf(acc[mt][nt][0], acc[mt][nt][1]));
            hi = fminf(hi, fminf(acc[mt][nt][2], acc[mt][nt][3]));
        }
        rmin[mt][0] = lo;
        rmin[mt][1] = hi;
    }
#pragma unroll
    for (int d = 1; d <= 2; d <<= 1)
#pragma unroll
        for (int mt = 0; mt < 4; ++mt)
#pragma unroll
            for (int h = 0; h < 2; ++h)
                rmin[mt][h] = fminf(rmin[mt][h],
                                    __shfl_xor_sync(0xffffffffu, rmin[mt][h], d));

    float* red = reinterpret_cast<float*>(smem + RED_OFF);
    __syncthreads();
    if ((lane & 3) == 0) {
        int gq = lane >> 2;
#pragma unroll
        for (int mt = 0; mt < 4; ++mt)
#pragma unroll
            for (int h = 0; h < 2; ++h) {
                int row = (warp_m * 4 + mt) * 16 + h * 8 + gq;
                red[row * 4 + warp_n] = rmin[mt][h];
            }
    }
    __syncthreads();
    if (tid < 128) {
        float m = fminf(fminf(red[tid * 4 + 0], red[tid * 4 + 1]),
                        fminf(red[tid * 4 + 2], red[tid * 4 + 3]));
        out[(size_t)b * 16384 + y * 128 + tid] = m * 2.0f;
    }
}

extern "C" void kernel_launch(void* const* d_in, const int* in_sizes, int n_in,
                              void* d_out, int out_size)
{
    const float* x  = (const float*)d_in[0];
    const float* Wt = (const float*)d_in[1];
    float* out = (float*)d_out;

    cudaFuncSetAttribute(conv_min_mma11_kernel,
                         cudaFuncAttributeMaxDynamicSharedMemorySize, SMEM_TOTAL);

    xi_kernel<<<17408, TPB>>>(x);                           // 32*32*128*34 / 256
    wxform_kernel<<<(4 * 18432 + TPB - 1) / TPB, TPB>>>(Wt);

    dim3 grid(128, 32);   // rows x batch
    conv_min_mma11_kernel<<<grid, TPB, SMEM_TOTAL>>>(out);
}